// round 9
// baseline (speedup 1.0000x reference)
#include <cuda_runtime.h>
#include <cstdint>

#define Bn 16
#define TNEW 8
#define Cdim 1024
#define Hn 16
#define HD 64
#define TPAST 4096
#define TFULL 4104
#define BHN 256     // Bn*Hn
#define NTOK 128    // Bn*TNEW
#define KSQ 8       // q GEMM K-split (KC = 128)
#define KSP 16      // proj GEMM K-split (KC = 64)
#define ASPLIT 4    // attention key-split
#define NCH 16      // 64-key chunks per attention block

// scratch (no cudaMalloc allowed)
__device__ __align__(16) float g_y[NTOK * Cdim];               // 512 KB
__device__ __align__(16) float g_part_a[KSP * 128 * 1024];     // q + proj partials
__device__ float g_pm[BHN * ASPLIT * 8];
__device__ float g_pl[BHN * ASPLIT * 8];
__device__ __align__(16) float g_po[BHN * ASPLIT * 8 * 64];    // 2 MB

__device__ __forceinline__ uint32_t smem_u32(const void* p) {
    return (uint32_t)__cvta_generic_to_shared(p);
}
__device__ __forceinline__ void cp16(uint32_t dst, const void* src) {
    asm volatile("cp.async.cg.shared.global [%0], [%1], 16;\n" :: "r"(dst), "l"(src));
}
__device__ __forceinline__ void cp_commit() {
    asm volatile("cp.async.commit_group;\n");
}
template <int N>
__device__ __forceinline__ void cp_wait() {
    asm volatile("cp.async.wait_group %0;\n" :: "n"(N));
}

// ---------------------------------------------------------------------------
// Split-K GEMM (q projection & output projection).
// ---------------------------------------------------------------------------
__global__ void __launch_bounds__(256) gemm_splitk(
    const float* __restrict__ A, const float* __restrict__ Bw,
    float* __restrict__ part, int N, int K, int KC)
{
    __shared__ float As[16][132];
    __shared__ float Bs[16][68];

    int n0 = blockIdx.x * 64;
    int kbase = blockIdx.y * KC;
    int t = threadIdx.x;
    int tx = t & 15, ty = t >> 4;

    const int ar = t >> 1, ac = (t & 1) * 8;
    const int br = t >> 2, bc = (t & 3) * 4;

    float acc[8][4] = {};

    const float* apg = &A[(size_t)ar * K + kbase + ac];
    const float* bpg = &Bw[(size_t)(n0 + br) * K + kbase + bc];
    float4 ra0 = *(const float4*)apg;
    float4 ra1 = *(const float4*)(apg + 4);
    float4 rb  = *(const float4*)bpg;

    for (int kk = 0; kk < KC; kk += 16) {
        As[ac + 0][ar] = ra0.x; As[ac + 1][ar] = ra0.y;
        As[ac + 2][ar] = ra0.z; As[ac + 3][ar] = ra0.w;
        As[ac + 4][ar] = ra1.x; As[ac + 5][ar] = ra1.y;
        As[ac + 6][ar] = ra1.z; As[ac + 7][ar] = ra1.w;
        Bs[bc + 0][br] = rb.x;  Bs[bc + 1][br] = rb.y;
        Bs[bc + 2][br] = rb.z;  Bs[bc + 3][br] = rb.w;
        __syncthreads();

        if (kk + 16 < KC) {
            ra0 = *(const float4*)(apg + kk + 16);
            ra1 = *(const float4*)(apg + kk + 20);
            rb  = *(const float4*)(bpg + kk + 16);
        }

        #pragma unroll
        for (int k = 0; k < 16; k++) {
            float4 a0 = *(const float4*)&As[k][ty * 8];
            float4 a1 = *(const float4*)&As[k][ty * 8 + 4];
            float4 b  = *(const float4*)&Bs[k][tx * 4];
            float a[8] = {a0.x, a0.y, a0.z, a0.w, a1.x, a1.y, a1.z, a1.w};
            float bb[4] = {b.x, b.y, b.z, b.w};
            #pragma unroll
            for (int i = 0; i < 8; i++)
                #pragma unroll
                for (int j = 0; j < 4; j++)
                    acc[i][j] += a[i] * bb[j];
        }
        __syncthreads();
    }

    float* pout = part + (size_t)blockIdx.y * 128 * N;
    #pragma unroll
    for (int i = 0; i < 8; i++) {
        int m = ty * 8 + i;
        float4 w = make_float4(acc[i][0], acc[i][1], acc[i][2], acc[i][3]);
        *(float4*)&pout[(size_t)m * N + n0 + tx * 4] = w;
    }
}

// reduce projection partials + bias -> out
__global__ void __launch_bounds__(256) reduce_proj(
    const float* __restrict__ part, const float* __restrict__ bias,
    float* __restrict__ out)
{
    int idx = blockIdx.x * 256 + threadIdx.x;   // 128 * 256
    int m = idx >> 8, n = idx & 255;
    float4 s = *(const float4*)&bias[n * 4];
    #pragma unroll
    for (int ks = 0; ks < KSP; ks++) {
        float4 p = *(const float4*)&part[((size_t)ks * 128 + m) * 1024 + n * 4];
        s.x += p.x; s.y += p.y; s.z += p.z; s.w += p.w;
    }
    *(float4*)&out[(size_t)m * 1024 + n * 4] = s;
}

// ---------------------------------------------------------------------------
// attn_split: grid (BHN, ASPLIT+1).
//  y < ASPLIT : pipelined past-key attention + cache copy (q reduced in-kernel)
//  y == ASPLIT: 128 tail-wave blocks compute the K/V projection tile (32x64,
//               full K) and write k_new/v_new + bias straight into the cache
//               tail.  These are last in bid order -> fill wave-2 slack.
// ---------------------------------------------------------------------------
__device__ __forceinline__ void softmax_update10(
    float* Ss, float* m_s, float* l_s, float* f_s, int lane, int wid)
{
    int j = wid;
    float v0 = Ss[lane * 10 + j];
    float v1 = Ss[(lane + 32) * 10 + j];
    float mx = fmaxf(v0, v1);
    #pragma unroll
    for (int o = 16; o; o >>= 1) mx = fmaxf(mx, __shfl_xor_sync(0xffffffffu, mx, o));
    float m_old = m_s[j];
    float m_new = fmaxf(m_old, mx);
    float p0 = __expf(v0 - m_new);
    float p1 = __expf(v1 - m_new);
    Ss[lane * 10 + j] = p0;
    Ss[(lane + 32) * 10 + j] = p1;
    float sum = p0 + p1;
    #pragma unroll
    for (int o = 16; o; o >>= 1) sum += __shfl_xor_sync(0xffffffffu, sum, o);
    if (lane == 0) {
        float f = __expf(m_old - m_new);
        l_s[j] = l_s[j] * f + sum;
        m_s[j] = m_new;
        f_s[j] = f;
    }
}

// dynamic smem layout (bytes):
//   qs: 0..2048 | k_sm: 2048..34816 (2x) | v_sm: 34816..51200 (1x)
//   Ss: 51200..53760 | m/l/f: 53760..53856 | red: 53856..55904
#define ATTN_SMEM 55904

__global__ void __launch_bounds__(256, 4) attn_split(
    const float* __restrict__ past_k, const float* __restrict__ past_v,
    float* __restrict__ kout, float* __restrict__ vout,
    const float* __restrict__ b_attn,
    const float* __restrict__ x, const float* __restrict__ W_attn)
{
    extern __shared__ char smraw[];
    int bh = blockIdx.x;
    int s  = blockIdx.y;
    int t = threadIdx.x, lane = t & 31, wid = t >> 5;

    // ================= kv-projection blocks (wave-2 filler) ================
    if (s == ASPLIT) {
        if (bh >= 128) return;
        float (*As)[36] = (float(*)[36])smraw;
        float (*Bs)[68] = (float(*)[68])(smraw + 4096);
        int m0 = (bh >> 5) * 32;           // 4 m-tiles of 32 tokens
        int n0 = (bh & 31) * 64;           // 32 n-tiles of 64 cols over 2048
        const float* Wkv = W_attn + (size_t)(1024 + n0) * 1024;
        int tx = t & 15, ty = t >> 4;
        float acc[2][4] = {};

        for (int kc = 0; kc < 1024; kc += 16) {
            if (t < 128) {
                int r = t >> 2, c = (t & 3) * 4;
                float4 v = *(const float4*)&x[(size_t)(m0 + r) * 1024 + kc + c];
                As[c + 0][r] = v.x; As[c + 1][r] = v.y;
                As[c + 2][r] = v.z; As[c + 3][r] = v.w;
            }
            {
                int r = t >> 2, c = (t & 3) * 4;
                float4 v = *(const float4*)&Wkv[(size_t)r * 1024 + kc + c];
                Bs[c + 0][r] = v.x; Bs[c + 1][r] = v.y;
                Bs[c + 2][r] = v.z; Bs[c + 3][r] = v.w;
            }
            __syncthreads();
            #pragma unroll
            for (int k = 0; k < 16; k++) {
                float a0 = As[k][ty * 2], a1 = As[k][ty * 2 + 1];
                float b0 = Bs[k][tx * 4], b1 = Bs[k][tx * 4 + 1];
                float b2 = Bs[k][tx * 4 + 2], b3 = Bs[k][tx * 4 + 3];
                acc[0][0] += a0 * b0; acc[0][1] += a0 * b1;
                acc[0][2] += a0 * b2; acc[0][3] += a0 * b3;
                acc[1][0] += a1 * b0; acc[1][1] += a1 * b1;
                acc[1][2] += a1 * b2; acc[1][3] += a1 * b3;
            }
            __syncthreads();
        }

        int n = n0 + tx * 4;               // within [0,2048); 64-col tile: one head
        int isv = n >> 10;
        int h = (n & 1023) >> 6;
        float4 bias4 = *(const float4*)&b_attn[1024 + n];
        float* dst = isv ? vout : kout;
        #pragma unroll
        for (int i = 0; i < 2; i++) {
            int tok = m0 + ty * 2 + i;
            int bb = tok >> 3, j = tok & 7;
            float4 w = make_float4(acc[i][0] + bias4.x, acc[i][1] + bias4.y,
                                   acc[i][2] + bias4.z, acc[i][3] + bias4.w);
            *(float4*)&dst[(((size_t)(bb * 16 + h) * TFULL) + TPAST + j) * 64 + (n & 63)] = w;
        }
        return;
    }

    // ========================= attention blocks ============================
    float*  qs   = (float*)smraw;
    float4* k_sm = (float4*)(smraw + 2048);
    float4* v_sm = (float4*)(smraw + 34816);
    float*  Ss   = (float*)(smraw + 51200);
    float*  m_s  = (float*)(smraw + 53760);
    float*  l_s  = m_s + 8;
    float*  f_s  = m_s + 16;
    float4* red  = (float4*)(smraw + 53856);

    int b = bh >> 4, h = bh & 15;

    const float4* ksrc = (const float4*)past_k + (size_t)bh * TPAST * 16;
    const float4* vsrc = (const float4*)past_v + (size_t)bh * TPAST * 16;
    float4* kdst = (float4*)kout + (size_t)bh * TFULL * 16;
    float4* vdst = (float4*)vout + (size_t)bh * TFULL * 16;

    const int ld_r = t >> 4, ld_d4 = t & 15;
    uint32_t k_b0 = smem_u32(k_sm), v_b0 = smem_u32(v_sm);

    const int c_begin = s * (TPAST / ASPLIT);

    // issue chunk-0 k prefetch first so DRAM starts streaming immediately
    #pragma unroll
    for (int it = 0; it < 4; it++) {
        int r = ld_r + it * 16;
        int sw = r * 16 + (ld_d4 ^ (r & 15));
        cp16(k_b0 + (uint32_t)sw * 16, ksrc + (size_t)(c_begin + r) * 16 + ld_d4);
    }
    cp_commit();

    // reduce this block's q slice from split-K partials (scale folded)
    for (int i = t; i < 512; i += 256) {
        int j = i >> 6, d = i & 63;
        int m = b * 8 + j, col = h * 64 + d;
        float sacc = b_attn[col];
        #pragma unroll
        for (int ks = 0; ks < KSQ; ks++)
            sacc += g_part_a[((size_t)ks * 128 + m) * 1024 + col];
        qs[i] = sacc * 0.125f;
    }
    if (t < 8) { m_s[t] = -3.0e38f; l_s[t] = 0.f; }

    const float4* q4 = (const float4*)qs;
    const float2* v2s = (const float2*)v_sm;

    const int j2 = (wid & 3) * 2;
    const int r_sc = (wid >> 2) * 32 + lane;
    const int jp = t >> 6;
    const int rh = (t >> 5) & 1;
    const int d2 = lane;

    float accA0 = 0.f, accA1 = 0.f, accB0 = 0.f, accB1 = 0.f;

    for (int ci = 0; ci < NCH; ci++) {
        int c0 = c_begin + ci * 64;
        int buf = ci & 1;
        cp_wait<0>();
        __syncthreads();       // sync_a: k(ci) + qs visible; accum(ci-1) done

        #pragma unroll
        for (int it = 0; it < 4; it++) {
            int r = ld_r + it * 16;
            int sw = r * 16 + (ld_d4 ^ (r & 15));
            cp16(v_b0 + (uint32_t)sw * 16, vsrc + (size_t)(c0 + r) * 16 + ld_d4);
        }
        cp_commit();

        bool more = (ci + 1 < NCH);
        if (more) {
            uint32_t kb = k_b0 + (uint32_t)(buf ^ 1) * 16384;
            #pragma unroll
            for (int it = 0; it < 4; it++) {
                int r = ld_r + it * 16;
                int sw = r * 16 + (ld_d4 ^ (r & 15));
                cp16(kb + (uint32_t)sw * 16, ksrc + (size_t)(c0 + 64 + r) * 16 + ld_d4);
            }
            cp_commit();
        }

        const float4* kbp = k_sm + buf * 1024;

        #pragma unroll
        for (int it = 0; it < 4; it++) {
            int r = ld_r + it * 16;
            int sw = r * 16 + (ld_d4 ^ (r & 15));
            __stcs(&kdst[(size_t)(c0 + r) * 16 + ld_d4], kbp[sw]);
        }

        {
            int r = r_sc;
            float s0 = 0.f, s1 = 0.f;
            #pragma unroll
            for (int d4 = 0; d4 < 16; d4++) {
                float4 kv = kbp[r * 16 + (d4 ^ (r & 15))];
                float4 qa = q4[j2 * 16 + d4];
                float4 qb = q4[(j2 + 1) * 16 + d4];
                s0 += kv.x * qa.x + kv.y * qa.y + kv.z * qa.z + kv.w * qa.w;
                s1 += kv.x * qb.x + kv.y * qb.y + kv.z * qb.z + kv.w * qb.w;
            }
            Ss[r * 10 + j2]     = s0;
            Ss[r * 10 + j2 + 1] = s1;
        }
        __syncthreads();       // sync_b
        softmax_update10(Ss, m_s, l_s, f_s, lane, wid);
        if (more) cp_wait<1>(); else cp_wait<0>();
        __syncthreads();       // sync_c

        {
            float f0 = f_s[2 * jp], f1 = f_s[2 * jp + 1];
            accA0 *= f0; accA1 *= f0; accB0 *= f1; accB1 *= f1;
        }
        #pragma unroll
        for (int it = 0; it < 4; it++) {
            int r = ld_r + it * 16;
            int sw = r * 16 + (ld_d4 ^ (r & 15));
            __stcs(&vdst[(size_t)(c0 + r) * 16 + ld_d4], v_sm[sw]);
        }
        {
            int d4 = d2 >> 1, dlo = d2 & 1;
            #pragma unroll 8
            for (int rr = 0; rr < 32; rr++) {
                int r = rh * 32 + rr;
                float2 p = *(const float2*)&Ss[r * 10 + 2 * jp];
                float2 vv = v2s[(r * 16 + (d4 ^ (r & 15))) * 2 + dlo];
                accA0 += p.x * vv.x; accA1 += p.x * vv.y;
                accB0 += p.y * vv.x; accB1 += p.y * vv.y;
            }
        }
    }
    __syncthreads();

    // cross-half reduce + store partials
    if (rh == 1) red[jp * 32 + d2] = make_float4(accA0, accA1, accB0, accB1);
    __syncthreads();
    if (rh == 0) {
        float4 o = red[jp * 32 + d2];
        accA0 += o.x; accA1 += o.y; accB0 += o.z; accB1 += o.w;
        int j0 = 2 * jp, j1 = 2 * jp + 1;
        size_t base = (size_t)(bh * ASPLIT + s) * 8;
        g_po[(base + j0) * 64 + 2 * d2]     = accA0;
        g_po[(base + j0) * 64 + 2 * d2 + 1] = accA1;
        g_po[(base + j1) * 64 + 2 * d2]     = accB0;
        g_po[(base + j1) * 64 + 2 * d2 + 1] = accB1;
    }
    if (t < 8) {
        g_pm[(bh * ASPLIT + s) * 8 + t] = m_s[t];
        g_pl[(bh * ASPLIT + s) * 8 + t] = l_s[t];
    }
}

// ---------------------------------------------------------------------------
// Combine: merge 4 past-split partials AND the 8 new causal keys -> g_y.
// Reduces q from partials; reads new k/v from the cache tail (written by the
// kv blocks of attn_split; ordered by the kernel boundary).
// ---------------------------------------------------------------------------
__global__ void __launch_bounds__(512) attn_combine(
    const float* __restrict__ kout, const float* __restrict__ vout,
    const float* __restrict__ b_attn)
{
    __shared__ float qs[512], kn[512], vn[512];
    __shared__ float Ss[64];

    int bh = blockIdx.x;
    int b = bh >> 4, h = bh & 15;
    int t = threadIdx.x;
    int j = t >> 6, d = t & 63;

    {
        int m = b * 8 + j, col = h * 64 + d;
        float sacc = b_attn[col];
        #pragma unroll
        for (int ks = 0; ks < KSQ; ks++)
            sacc += g_part_a[((size_t)ks * 128 + m) * 1024 + col];
        qs[t] = sacc * 0.125f;
    }
    kn[t] = kout[((size_t)bh * TFULL + TPAST + j) * 64 + d];
    vn[t] = vout[((size_t)bh * TFULL + TPAST + j) * 64 + d];
    __syncthreads();

    if (t < 64) {
        int jq = t >> 3, r = t & 7;
        float sc = -3.0e38f;
        if (r <= jq) {
            float a = 0.f;
            #pragma unroll
            for (int dd = 0; dd < 64; dd++)
                a += qs[jq * 64 + dd] * kn[r * 64 + dd];
            sc = a;
        }
        Ss[t] = sc;
    }
    __syncthreads();

    float mm[ASPLIT], ll[ASPLIT];
    float m_g = -3.0e38f;
    #pragma unroll
    for (int s = 0; s < ASPLIT; s++) {
        mm[s] = g_pm[(bh * ASPLIT + s) * 8 + j];
        ll[s] = g_pl[(bh * ASPLIT + s) * 8 + j];
        m_g = fmaxf(m_g, mm[s]);
    }
    float sc[8];
    #pragma unroll
    for (int r = 0; r < 8; r++) {
        sc[r] = Ss[j * 8 + r];
        m_g = fmaxf(m_g, sc[r]);
    }
    float l_g = 0.f, o = 0.f;
    #pragma unroll
    for (int s = 0; s < ASPLIT; s++) {
        float w = __expf(mm[s] - m_g);
        l_g += ll[s] * w;
        o += g_po[((size_t)(bh * ASPLIT + s) * 8 + j) * 64 + d] * w;
    }
    #pragma unroll
    for (int r = 0; r < 8; r++) {
        float p = __expf(sc[r] - m_g);
        l_g += p;
        o += p * vn[r * 64 + d];
    }
    g_y[(size_t)(b * 8 + j) * Cdim + h * 64 + d] = o / l_g;
}

// ---------------------------------------------------------------------------
// kernel_launch (single stream):
//   gemm_q -> attn_split(grid 256x5: attention + wave-2 kv projection)
//          -> attn_combine -> proj gemm -> reduce_proj
// ---------------------------------------------------------------------------
extern "C" void kernel_launch(void* const* d_in, const int* in_sizes, int n_in,
                              void* d_out, int out_size)
{
    const float* x      = (const float*)d_in[0];
    const float* past_k = (const float*)d_in[1];
    const float* past_v = (const float*)d_in[2];
    const float* W_attn = (const float*)d_in[3];
    const float* b_attn = (const float*)d_in[4];
    const float* W_proj = (const float*)d_in[5];
    const float* b_proj = (const float*)d_in[6];

    float* out  = (float*)d_out;
    float* kout = out + (size_t)NTOK * Cdim;
    float* vout = kout + (size_t)BHN * TFULL * HD;

    float* y_ptr  = nullptr;
    float* pa_ptr = nullptr;
    cudaGetSymbolAddress((void**)&y_ptr, g_y);
    cudaGetSymbolAddress((void**)&pa_ptr, g_part_a);

    static int init_done = 0;
    if (!init_done) {
        cudaFuncSetAttribute(attn_split,
            cudaFuncAttributeMaxDynamicSharedMemorySize, ATTN_SMEM);
        init_done = 1;
    }

    // 1) q projection partials (attn/combine blocks finish the reduction)
    gemm_splitk<<<dim3(16, KSQ), 256>>>(x, W_attn, pa_ptr, 1024, 1024, 128);

    // 2) attention over past keys + cache copy; kv projection rides wave 2
    attn_split<<<dim3(BHN, ASPLIT + 1), 256, ATTN_SMEM>>>(
        past_k, past_v, kout, vout, b_attn, x, W_attn);

    // 3) merge split partials + new causal keys
    attn_combine<<<BHN, 512>>>(kout, vout, b_attn);

    // 4) output projection
    gemm_splitk<<<dim3(16, KSP), 256>>>(y_ptr, W_proj, pa_ptr, 1024, 1024, 64);
    reduce_proj<<<128, 256>>>(pa_ptr, b_proj, out);
}

// round 10
// speedup vs baseline: 1.0863x; 1.0863x over previous
#include <cuda_runtime.h>
#include <cstdint>

#define Bn 16
#define TNEW 8
#define Cdim 1024
#define Hn 16
#define HD 64
#define TPAST 4096
#define TFULL 4104
#define BHN 256     // Bn*Hn
#define NTOK 128    // Bn*TNEW
#define KSQ 8       // QKV GEMM K-split (KC = 128)
#define KSP 16      // proj GEMM K-split (KC = 64)
#define ASPLIT 4    // attention key-split
#define NCH 16      // 64-key chunks per attention block

// scratch (no cudaMalloc allowed)
__device__ __align__(16) float g_y[NTOK * Cdim];               // 512 KB
__device__ __align__(16) float g_part[KSQ * 128 * 3072];       // 12.6 MB (qkv / proj partials)
__device__ float g_pm[BHN * ASPLIT * 8];
__device__ float g_pl[BHN * ASPLIT * 8];
__device__ __align__(16) float g_po[BHN * ASPLIT * 8 * 64];    // 2 MB

__device__ __forceinline__ uint32_t smem_u32(const void* p) {
    return (uint32_t)__cvta_generic_to_shared(p);
}
__device__ __forceinline__ void cp16(uint32_t dst, const void* src) {
    asm volatile("cp.async.cg.shared.global [%0], [%1], 16;\n" :: "r"(dst), "l"(src));
}
__device__ __forceinline__ void cp_commit() {
    asm volatile("cp.async.commit_group;\n");
}
template <int N>
__device__ __forceinline__ void cp_wait() {
    asm volatile("cp.async.wait_group %0;\n" :: "n"(N));
}

// ---------------------------------------------------------------------------
// Split-K GEMM with register double-buffering of the global loads.
// part[ks][m][n] = sum_{k in chunk} A[m][k]*Bw[n][k].  M fixed = 128.
// ---------------------------------------------------------------------------
__global__ void __launch_bounds__(256) gemm_splitk(
    const float* __restrict__ A, const float* __restrict__ Bw,
    float* __restrict__ part, int N, int K, int KC)
{
    __shared__ float As[16][132];
    __shared__ float Bs[16][68];

    int n0 = blockIdx.x * 64;
    int kbase = blockIdx.y * KC;
    int t = threadIdx.x;
    int tx = t & 15, ty = t >> 4;

    const int ar = t >> 1, ac = (t & 1) * 8;
    const int br = t >> 2, bc = (t & 3) * 4;

    float acc[8][4] = {};

    const float* apg = &A[(size_t)ar * K + kbase + ac];
    const float* bpg = &Bw[(size_t)(n0 + br) * K + kbase + bc];
    float4 ra0 = *(const float4*)apg;
    float4 ra1 = *(const float4*)(apg + 4);
    float4 rb  = *(const float4*)bpg;

    for (int kk = 0; kk < KC; kk += 16) {
        As[ac + 0][ar] = ra0.x; As[ac + 1][ar] = ra0.y;
        As[ac + 2][ar] = ra0.z; As[ac + 3][ar] = ra0.w;
        As[ac + 4][ar] = ra1.x; As[ac + 5][ar] = ra1.y;
        As[ac + 6][ar] = ra1.z; As[ac + 7][ar] = ra1.w;
        Bs[bc + 0][br] = rb.x;  Bs[bc + 1][br] = rb.y;
        Bs[bc + 2][br] = rb.z;  Bs[bc + 3][br] = rb.w;
        __syncthreads();

        if (kk + 16 < KC) {
            ra0 = *(const float4*)(apg + kk + 16);
            ra1 = *(const float4*)(apg + kk + 20);
            rb  = *(const float4*)(bpg + kk + 16);
        }

        #pragma unroll
        for (int k = 0; k < 16; k++) {
            float4 a0 = *(const float4*)&As[k][ty * 8];
            float4 a1 = *(const float4*)&As[k][ty * 8 + 4];
            float4 b  = *(const float4*)&Bs[k][tx * 4];
            float a[8] = {a0.x, a0.y, a0.z, a0.w, a1.x, a1.y, a1.z, a1.w};
            float bb[4] = {b.x, b.y, b.z, b.w};
            #pragma unroll
            for (int i = 0; i < 8; i++)
                #pragma unroll
                for (int j = 0; j < 4; j++)
                    acc[i][j] += a[i] * bb[j];
        }
        __syncthreads();
    }

    float* pout = part + (size_t)blockIdx.y * 128 * N;
    #pragma unroll
    for (int i = 0; i < 8; i++) {
        int m = ty * 8 + i;
        float4 w = make_float4(acc[i][0], acc[i][1], acc[i][2], acc[i][3]);
        *(float4*)&pout[(size_t)m * N + n0 + tx * 4] = w;
    }
}

// reduce projection partials + bias -> out
__global__ void __launch_bounds__(256) reduce_proj(
    const float* __restrict__ part, const float* __restrict__ bias,
    float* __restrict__ out)
{
    int idx = blockIdx.x * 256 + threadIdx.x;   // 128 * 256
    int m = idx >> 8, n = idx & 255;
    float4 s = *(const float4*)&bias[n * 4];
    #pragma unroll
    for (int ks = 0; ks < KSP; ks++) {
        float4 p = *(const float4*)&part[((size_t)ks * 128 + m) * 1024 + n * 4];
        s.x += p.x; s.y += p.y; s.z += p.z; s.w += p.w;
    }
    *(float4*)&out[(size_t)m * 1024 + n * 4] = s;
}

// ---------------------------------------------------------------------------
// Pipelined split attention over PAST keys.  grid (BHN, ASPLIT).
// Reduces its own q slice from QKV split-K partials (3072-wide layout).
// k double-buffered cp.async; v single-buffered deferred; fused cache copy.
// ---------------------------------------------------------------------------
__device__ __forceinline__ void softmax_update10(
    float* Ss, float* m_s, float* l_s, float* f_s, int lane, int wid)
{
    int j = wid;
    float v0 = Ss[lane * 10 + j];
    float v1 = Ss[(lane + 32) * 10 + j];
    float mx = fmaxf(v0, v1);
    #pragma unroll
    for (int o = 16; o; o >>= 1) mx = fmaxf(mx, __shfl_xor_sync(0xffffffffu, mx, o));
    float m_old = m_s[j];
    float m_new = fmaxf(m_old, mx);
    float p0 = __expf(v0 - m_new);
    float p1 = __expf(v1 - m_new);
    Ss[lane * 10 + j] = p0;
    Ss[(lane + 32) * 10 + j] = p1;
    float sum = p0 + p1;
    #pragma unroll
    for (int o = 16; o; o >>= 1) sum += __shfl_xor_sync(0xffffffffu, sum, o);
    if (lane == 0) {
        float f = __expf(m_old - m_new);
        l_s[j] = l_s[j] * f + sum;
        m_s[j] = m_new;
        f_s[j] = f;
    }
}

// dynamic smem layout (bytes):
//   qs: 0..2048 | k_sm: 2048..34816 (2x) | v_sm: 34816..51200 (1x)
//   Ss: 51200..53760 | m/l/f: 53760..53856 | red: 53856..55904
#define ATTN_SMEM 55904

__global__ void __launch_bounds__(256, 4) attn_split(
    const float* __restrict__ past_k, const float* __restrict__ past_v,
    float* __restrict__ kout, float* __restrict__ vout,
    const float* __restrict__ b_attn)
{
    extern __shared__ char smraw[];
    float*  qs   = (float*)smraw;
    float4* k_sm = (float4*)(smraw + 2048);
    float4* v_sm = (float4*)(smraw + 34816);
    float*  Ss   = (float*)(smraw + 51200);
    float*  m_s  = (float*)(smraw + 53760);
    float*  l_s  = m_s + 8;
    float*  f_s  = m_s + 16;
    float4* red  = (float4*)(smraw + 53856);

    int bh = blockIdx.x;
    int s  = blockIdx.y;
    int b = bh >> 4, h = bh & 15;
    int t = threadIdx.x, lane = t & 31, wid = t >> 5;

    const float4* ksrc = (const float4*)past_k + (size_t)bh * TPAST * 16;
    const float4* vsrc = (const float4*)past_v + (size_t)bh * TPAST * 16;
    float4* kdst = (float4*)kout + (size_t)bh * TFULL * 16;
    float4* vdst = (float4*)vout + (size_t)bh * TFULL * 16;

    const int ld_r = t >> 4, ld_d4 = t & 15;
    uint32_t k_b0 = smem_u32(k_sm), v_b0 = smem_u32(v_sm);

    const int c_begin = s * (TPAST / ASPLIT);

    // issue chunk-0 k prefetch first so DRAM starts streaming immediately
    #pragma unroll
    for (int it = 0; it < 4; it++) {
        int r = ld_r + it * 16;
        int sw = r * 16 + (ld_d4 ^ (r & 15));
        cp16(k_b0 + (uint32_t)sw * 16, ksrc + (size_t)(c_begin + r) * 16 + ld_d4);
    }
    cp_commit();

    // reduce this block's q slice from QKV split-K partials (scale folded)
    for (int i = t; i < 512; i += 256) {
        int j = i >> 6, d = i & 63;
        int m = b * 8 + j, col = h * 64 + d;
        float sacc = b_attn[col];
        #pragma unroll
        for (int ks = 0; ks < KSQ; ks++)
            sacc += g_part[((size_t)ks * 128 + m) * 3072 + col];
        qs[i] = sacc * 0.125f;
    }
    if (t < 8) { m_s[t] = -3.0e38f; l_s[t] = 0.f; }

    const float4* q4 = (const float4*)qs;
    const float2* v2s = (const float2*)v_sm;

    const int j2 = (wid & 3) * 2;
    const int r_sc = (wid >> 2) * 32 + lane;
    const int jp = t >> 6;
    const int rh = (t >> 5) & 1;
    const int d2 = lane;

    float accA0 = 0.f, accA1 = 0.f, accB0 = 0.f, accB1 = 0.f;

    for (int ci = 0; ci < NCH; ci++) {
        int c0 = c_begin + ci * 64;
        int buf = ci & 1;
        cp_wait<0>();
        __syncthreads();       // sync_a: k(ci) + qs visible; accum(ci-1) done

        #pragma unroll
        for (int it = 0; it < 4; it++) {
            int r = ld_r + it * 16;
            int sw = r * 16 + (ld_d4 ^ (r & 15));
            cp16(v_b0 + (uint32_t)sw * 16, vsrc + (size_t)(c0 + r) * 16 + ld_d4);
        }
        cp_commit();

        bool more = (ci + 1 < NCH);
        if (more) {
            uint32_t kb = k_b0 + (uint32_t)(buf ^ 1) * 16384;
            #pragma unroll
            for (int it = 0; it < 4; it++) {
                int r = ld_r + it * 16;
                int sw = r * 16 + (ld_d4 ^ (r & 15));
                cp16(kb + (uint32_t)sw * 16, ksrc + (size_t)(c0 + 64 + r) * 16 + ld_d4);
            }
            cp_commit();
        }

        const float4* kbp = k_sm + buf * 1024;

        #pragma unroll
        for (int it = 0; it < 4; it++) {
            int r = ld_r + it * 16;
            int sw = r * 16 + (ld_d4 ^ (r & 15));
            __stcs(&kdst[(size_t)(c0 + r) * 16 + ld_d4], kbp[sw]);
        }

        {
            int r = r_sc;
            float s0 = 0.f, s1 = 0.f;
            #pragma unroll
            for (int d4 = 0; d4 < 16; d4++) {
                float4 kv = kbp[r * 16 + (d4 ^ (r & 15))];
                float4 qa = q4[j2 * 16 + d4];
                float4 qb = q4[(j2 + 1) * 16 + d4];
                s0 += kv.x * qa.x + kv.y * qa.y + kv.z * qa.z + kv.w * qa.w;
                s1 += kv.x * qb.x + kv.y * qb.y + kv.z * qb.z + kv.w * qb.w;
            }
            Ss[r * 10 + j2]     = s0;
            Ss[r * 10 + j2 + 1] = s1;
        }
        __syncthreads();       // sync_b
        softmax_update10(Ss, m_s, l_s, f_s, lane, wid);
        if (more) cp_wait<1>(); else cp_wait<0>();
        __syncthreads();       // sync_c

        {
            float f0 = f_s[2 * jp], f1 = f_s[2 * jp + 1];
            accA0 *= f0; accA1 *= f0; accB0 *= f1; accB1 *= f1;
        }
        #pragma unroll
        for (int it = 0; it < 4; it++) {
            int r = ld_r + it * 16;
            int sw = r * 16 + (ld_d4 ^ (r & 15));
            __stcs(&vdst[(size_t)(c0 + r) * 16 + ld_d4], v_sm[sw]);
        }
        {
            int d4 = d2 >> 1, dlo = d2 & 1;
            #pragma unroll 8
            for (int rr = 0; rr < 32; rr++) {
                int r = rh * 32 + rr;
                float2 p = *(const float2*)&Ss[r * 10 + 2 * jp];
                float2 vv = v2s[(r * 16 + (d4 ^ (r & 15))) * 2 + dlo];
                accA0 += p.x * vv.x; accA1 += p.x * vv.y;
                accB0 += p.y * vv.x; accB1 += p.y * vv.y;
            }
        }
    }
    __syncthreads();

    // cross-half reduce + store partials
    if (rh == 1) red[jp * 32 + d2] = make_float4(accA0, accA1, accB0, accB1);
    __syncthreads();
    if (rh == 0) {
        float4 o = red[jp * 32 + d2];
        accA0 += o.x; accA1 += o.y; accB0 += o.z; accB1 += o.w;
        int j0 = 2 * jp, j1 = 2 * jp + 1;
        size_t base = (size_t)(bh * ASPLIT + s) * 8;
        g_po[(base + j0) * 64 + 2 * d2]     = accA0;
        g_po[(base + j0) * 64 + 2 * d2 + 1] = accA1;
        g_po[(base + j1) * 64 + 2 * d2]     = accB0;
        g_po[(base + j1) * 64 + 2 * d2 + 1] = accB1;
    }
    if (t < 8) {
        g_pm[(bh * ASPLIT + s) * 8 + t] = m_s[t];
        g_pl[(bh * ASPLIT + s) * 8 + t] = l_s[t];
    }
}

// ---------------------------------------------------------------------------
// Combine: reduce k_new/v_new from QKV partials (+bias), scatter them into
// the cache tail, evaluate the 8x8 causal block, merge with the 4 past-split
// partials -> g_y.  One block per (b,h), 512 threads.
// ---------------------------------------------------------------------------
__global__ void __launch_bounds__(512) attn_combine(
    float* __restrict__ kout, float* __restrict__ vout,
    const float* __restrict__ b_attn)
{
    __shared__ float qs[512], kn[512], vn[512];
    __shared__ float Ss[64];

    int bh = blockIdx.x;
    int b = bh >> 4, h = bh & 15;
    int t = threadIdx.x;
    int j = t >> 6, d = t & 63;
    int m = b * 8 + j;

    // reduce q (scaled), k_new, v_new from QKV split-K partials
    {
        int colq = h * 64 + d;
        int colk = 1024 + colq;
        int colv = 2048 + colq;
        float sq = b_attn[colq], sk = b_attn[colk], sv = b_attn[colv];
        #pragma unroll
        for (int ks = 0; ks < KSQ; ks++) {
            const float* p = &g_part[((size_t)ks * 128 + m) * 3072];
            sq += p[colq];
            sk += p[colk];
            sv += p[colv];
        }
        qs[t] = sq * 0.125f;
        kn[t] = sk;
        vn[t] = sv;
        // scatter new rows into the cache tail (part of the output)
        size_t goff = ((size_t)bh * TFULL + TPAST + j) * 64 + d;
        kout[goff] = sk;
        vout[goff] = sv;
    }
    __syncthreads();

    // scores for the 8x8 causal block (64 threads)
    if (t < 64) {
        int jq = t >> 3, r = t & 7;
        float sc = -3.0e38f;
        if (r <= jq) {
            float a = 0.f;
            #pragma unroll
            for (int dd = 0; dd < 64; dd++)
                a += qs[jq * 64 + dd] * kn[r * 64 + dd];
            sc = a;
        }
        Ss[t] = sc;
    }
    __syncthreads();

    float mm[ASPLIT], ll[ASPLIT];
    float m_g = -3.0e38f;
    #pragma unroll
    for (int s = 0; s < ASPLIT; s++) {
        mm[s] = g_pm[(bh * ASPLIT + s) * 8 + j];
        ll[s] = g_pl[(bh * ASPLIT + s) * 8 + j];
        m_g = fmaxf(m_g, mm[s]);
    }
    float sc[8];
    #pragma unroll
    for (int r = 0; r < 8; r++) {
        sc[r] = Ss[j * 8 + r];
        m_g = fmaxf(m_g, sc[r]);
    }
    float l_g = 0.f, o = 0.f;
    #pragma unroll
    for (int s = 0; s < ASPLIT; s++) {
        float w = __expf(mm[s] - m_g);
        l_g += ll[s] * w;
        o += g_po[((size_t)(bh * ASPLIT + s) * 8 + j) * 64 + d] * w;
    }
    #pragma unroll
    for (int r = 0; r < 8; r++) {
        float p = __expf(sc[r] - m_g);   // exp(-inf - m) = 0 handles mask
        l_g += p;
        o += p * vn[r * 64 + d];
    }
    g_y[(size_t)m * Cdim + h * 64 + d] = o / l_g;
}

// ---------------------------------------------------------------------------
// kernel_launch (single stream, 5 kernels):
//   gemm_qkv -> attn_split(q-reduce inside) -> attn_combine(kv-reduce +
//   scatter + merge) -> gemm_proj -> reduce_proj
// ---------------------------------------------------------------------------
extern "C" void kernel_launch(void* const* d_in, const int* in_sizes, int n_in,
                              void* d_out, int out_size)
{
    const float* x      = (const float*)d_in[0];
    const float* past_k = (const float*)d_in[1];
    const float* past_v = (const float*)d_in[2];
    const float* W_attn = (const float*)d_in[3];
    const float* b_attn = (const float*)d_in[4];
    const float* W_proj = (const float*)d_in[5];
    const float* b_proj = (const float*)d_in[6];

    float* out  = (float*)d_out;
    float* kout = out + (size_t)NTOK * Cdim;
    float* vout = kout + (size_t)BHN * TFULL * HD;

    float* y_ptr  = nullptr;
    float* pp_ptr = nullptr;
    cudaGetSymbolAddress((void**)&y_ptr, g_y);
    cudaGetSymbolAddress((void**)&pp_ptr, g_part);

    static int init_done = 0;
    if (!init_done) {
        cudaFuncSetAttribute(attn_split,
            cudaFuncAttributeMaxDynamicSharedMemorySize, ATTN_SMEM);
        init_done = 1;
    }

    // 1) fused QKV projection partials (consumers finish the reduction)
    gemm_splitk<<<dim3(48, KSQ), 256>>>(x, W_attn, pp_ptr, 3072, 1024, 128);

    // 2) attention over past keys + cache copy (q reduced in-kernel)
    attn_split<<<dim3(BHN, ASPLIT), 256, ATTN_SMEM>>>(
        past_k, past_v, kout, vout, b_attn);

    // 3) kv reduce + scatter + causal tail + merge
    attn_combine<<<BHN, 512>>>(kout, vout, b_attn);

    // 4) output projection (split-K, KC=64) -- g_part is free again
    gemm_splitk<<<dim3(16, KSP), 256>>>(y_ptr, W_proj, pp_ptr, 1024, 1024, 64);
    reduce_proj<<<128, 256>>>(pp_ptr, b_proj, out);
}

// round 11
// speedup vs baseline: 1.1256x; 1.0361x over previous
#include <cuda_runtime.h>
#include <cstdint>

#define Bn 16
#define TNEW 8
#define Cdim 1024
#define Hn 16
#define HD 64
#define TPAST 4096
#define TFULL 4104
#define BHN 256     // Bn*Hn
#define NTOK 128    // Bn*TNEW
#define KSQ 8       // QKV GEMM K-split (KC = 128)
#define KSP 16      // proj GEMM K-split (KC = 64)
#define ASPLIT 4    // attention key-split
#define NCH 16      // 64-key chunks per attention block

// scratch (no cudaMalloc allowed)
__device__ __align__(16) float g_qkv[NTOK * 3 * Cdim];        // 1.5 MB
__device__ __align__(16) float g_y[NTOK * Cdim];              // 512 KB
__device__ __align__(16) float g_part[KSQ * 128 * 3072];      // 12.6 MB
__device__ float g_pm[BHN * ASPLIT * 8];
__device__ float g_pl[BHN * ASPLIT * 8];
__device__ __align__(16) float g_po[BHN * ASPLIT * 8 * 64];   // 2 MB

__device__ __forceinline__ uint32_t smem_u32(const void* p) {
    return (uint32_t)__cvta_generic_to_shared(p);
}
__device__ __forceinline__ void cp16(uint32_t dst, const void* src) {
    asm volatile("cp.async.cg.shared.global [%0], [%1], 16;\n" :: "r"(dst), "l"(src));
}
__device__ __forceinline__ void cp_commit() {
    asm volatile("cp.async.commit_group;\n");
}
template <int N>
__device__ __forceinline__ void cp_wait() {
    asm volatile("cp.async.wait_group %0;\n" :: "n"(N));
}

// ---------------------------------------------------------------------------
// tf32 split-MMA GEMM (Markidis 2-term split -> fp32-class accuracy).
// part[ks][m][n] = sum_{k in chunk} A[m][k]*Bw[n][k].  M fixed = 128.
// Block tile: 128m x 64n, 256 threads (8 warps as 4m x 2n), staged 32-k chunks.
// ---------------------------------------------------------------------------
__device__ __forceinline__ void tf32_split(float a, uint32_t& hi, uint32_t& lo) {
    uint32_t h;
    asm("cvt.rna.tf32.f32 %0, %1;" : "=r"(h) : "f"(a));
    float r = a - __uint_as_float(h);
    uint32_t l;
    asm("cvt.rna.tf32.f32 %0, %1;" : "=r"(l) : "f"(r));
    hi = h; lo = l;
}

__device__ __forceinline__ void mma_tf32(float* d, const uint32_t* a, const uint32_t* b) {
    asm volatile(
        "mma.sync.aligned.m16n8k8.row.col.f32.tf32.tf32.f32 "
        "{%0,%1,%2,%3}, {%4,%5,%6,%7}, {%8,%9}, {%0,%1,%2,%3};\n"
        : "+f"(d[0]), "+f"(d[1]), "+f"(d[2]), "+f"(d[3])
        : "r"(a[0]), "r"(a[1]), "r"(a[2]), "r"(a[3]), "r"(b[0]), "r"(b[1]));
}

__global__ void __launch_bounds__(256) gemm_mma_splitk(
    const float* __restrict__ A, const float* __restrict__ Bw,
    float* __restrict__ part, int N, int K, int KC)
{
    __shared__ float As[128][36];   // pad 36: conflict-free fragment gathers
    __shared__ float Ws[64][36];

    int n0 = blockIdx.x * 64;
    int kbase = blockIdx.y * KC;
    int t = threadIdx.x, lane = t & 31, wid = t >> 5;
    int grp = lane >> 2, tig = lane & 3;
    int wm = (wid >> 1) * 32;       // warp m offset (4 warps over 128m)
    int wn = (wid & 1) * 32;        // warp n offset (2 warps over 64n)

    float d[2][4][4];
    #pragma unroll
    for (int i = 0; i < 2; i++)
        #pragma unroll
        for (int j = 0; j < 4; j++)
            #pragma unroll
            for (int r = 0; r < 4; r++) d[i][j][r] = 0.f;

    for (int kk = 0; kk < KC; kk += 32) {
        // stage A 128x32
        #pragma unroll
        for (int it = 0; it < 4; it++) {
            int idx = t + it * 256;         // 0..1023
            int row = idx >> 3, c4 = (idx & 7) * 4;
            float4 v = *(const float4*)&A[(size_t)row * K + kbase + kk + c4];
            As[row][c4] = v.x; As[row][c4 + 1] = v.y;
            As[row][c4 + 2] = v.z; As[row][c4 + 3] = v.w;
        }
        // stage W 64x32
        #pragma unroll
        for (int it = 0; it < 2; it++) {
            int idx = t + it * 256;         // 0..511
            int row = idx >> 3, c4 = (idx & 7) * 4;
            float4 v = *(const float4*)&Bw[(size_t)(n0 + row) * K + kbase + kk + c4];
            Ws[row][c4] = v.x; Ws[row][c4 + 1] = v.y;
            Ws[row][c4 + 2] = v.z; Ws[row][c4 + 3] = v.w;
        }
        __syncthreads();

        #pragma unroll
        for (int ks = 0; ks < 4; ks++) {
            int kb = ks * 8;
            uint32_t ah[2][4], al[2][4];
            #pragma unroll
            for (int i = 0; i < 2; i++) {
                int mb = wm + i * 16;
                tf32_split(As[mb + grp][kb + tig],         ah[i][0], al[i][0]);
                tf32_split(As[mb + grp + 8][kb + tig],     ah[i][1], al[i][1]);
                tf32_split(As[mb + grp][kb + tig + 4],     ah[i][2], al[i][2]);
                tf32_split(As[mb + grp + 8][kb + tig + 4], ah[i][3], al[i][3]);
            }
            uint32_t bh[4][2], bl[4][2];
            #pragma unroll
            for (int j = 0; j < 4; j++) {
                int nb = wn + j * 8;
                tf32_split(Ws[nb + grp][kb + tig],     bh[j][0], bl[j][0]);
                tf32_split(Ws[nb + grp][kb + tig + 4], bh[j][1], bl[j][1]);
            }
            #pragma unroll
            for (int i = 0; i < 2; i++)
                #pragma unroll
                for (int j = 0; j < 4; j++) {
                    mma_tf32(d[i][j], ah[i], bh[j]);   // hi*hi
                    mma_tf32(d[i][j], ah[i], bl[j]);   // hi*lo
                    mma_tf32(d[i][j], al[i], bh[j]);   // lo*hi
                }
        }
        __syncthreads();
    }

    // epilogue: write partials (fragment layout -> (m, n) coords)
    float* pout = part + (size_t)blockIdx.y * 128 * N;
    #pragma unroll
    for (int i = 0; i < 2; i++) {
        #pragma unroll
        for (int j = 0; j < 4; j++) {
            int m = wm + i * 16 + grp;
            int n = n0 + wn + j * 8 + tig * 2;
            *(float2*)&pout[(size_t)m * N + n]       = make_float2(d[i][j][0], d[i][j][1]);
            *(float2*)&pout[(size_t)(m + 8) * N + n] = make_float2(d[i][j][2], d[i][j][3]);
        }
    }
}

// reduce QKV partials + bias -> g_qkv, AND scatter new k/v rows into caches
__global__ void __launch_bounds__(256) reduce_qkv(
    const float* __restrict__ part, const float* __restrict__ bias,
    float* __restrict__ out, float* __restrict__ kout, float* __restrict__ vout)
{
    int idx = blockIdx.x * 256 + threadIdx.x;   // 128 * 768
    int m = idx / 768, n = idx % 768;
    float4 s = *(const float4*)&bias[n * 4];
    #pragma unroll
    for (int ks = 0; ks < KSQ; ks++) {
        float4 p = *(const float4*)&part[((size_t)ks * 128 + m) * 3072 + n * 4];
        s.x += p.x; s.y += p.y; s.z += p.z; s.w += p.w;
    }
    *(float4*)&out[(size_t)m * 3072 + n * 4] = s;

    int c = n * 4;
    if (c >= 1024) {
        int isv = c >= 2048;
        int cc = c - (isv ? 2048 : 1024);
        int hh = cc >> 6, d = cc & 63;
        int bb = m >> 3, j = m & 7;
        float* dst = isv ? vout : kout;
        *(float4*)&dst[(((size_t)(bb * 16 + hh)) * TFULL + TPAST + j) * 64 + d] = s;
    }
}

// reduce projection partials + bias -> out
__global__ void __launch_bounds__(256) reduce_proj(
    const float* __restrict__ part, const float* __restrict__ bias,
    float* __restrict__ out)
{
    int idx = blockIdx.x * 256 + threadIdx.x;   // 128 * 256
    int m = idx >> 8, n = idx & 255;
    float4 s = *(const float4*)&bias[n * 4];
    #pragma unroll
    for (int ks = 0; ks < KSP; ks++) {
        float4 p = *(const float4*)&part[((size_t)ks * 128 + m) * 1024 + n * 4];
        s.x += p.x; s.y += p.y; s.z += p.z; s.w += p.w;
    }
    *(float4*)&out[(size_t)m * 1024 + n * 4] = s;
}

// ---------------------------------------------------------------------------
// Pipelined split attention (R6-exact).  grid (BHN, ASPLIT).  64-key chunks.
// k double-buffered cp.async; v single-buffered with deferred wait; fused
// cache copy.  55.9KB smem -> 4 blocks/SM.
// ---------------------------------------------------------------------------
__device__ __forceinline__ void softmax_update10(
    float* Ss, float* m_s, float* l_s, float* f_s, int lane, int wid)
{
    int j = wid;                       // warp w owns query row j=w
    float v0 = Ss[lane * 10 + j];
    float v1 = Ss[(lane + 32) * 10 + j];
    float mx = fmaxf(v0, v1);
    #pragma unroll
    for (int o = 16; o; o >>= 1) mx = fmaxf(mx, __shfl_xor_sync(0xffffffffu, mx, o));
    float m_old = m_s[j];
    float m_new = fmaxf(m_old, mx);
    float p0 = __expf(v0 - m_new);
    float p1 = __expf(v1 - m_new);
    Ss[lane * 10 + j] = p0;
    Ss[(lane + 32) * 10 + j] = p1;
    float sum = p0 + p1;
    #pragma unroll
    for (int o = 16; o; o >>= 1) sum += __shfl_xor_sync(0xffffffffu, sum, o);
    if (lane == 0) {
        float f = __expf(m_old - m_new);
        l_s[j] = l_s[j] * f + sum;
        m_s[j] = m_new;
        f_s[j] = f;
    }
}

// dynamic smem layout (bytes):
//   qs: 0..2048 | k_sm: 2048..34816 (2x) | v_sm: 34816..51200 (1x)
//   Ss: 51200..53760 | m/l/f: 53760..53856 | red: 53856..55904
#define ATTN_SMEM 55904

__global__ void __launch_bounds__(256, 4) attn_split(
    const float* __restrict__ past_k, const float* __restrict__ past_v,
    float* __restrict__ kout, float* __restrict__ vout)
{
    extern __shared__ char smraw[];
    float*  qs   = (float*)smraw;
    float4* k_sm = (float4*)(smraw + 2048);
    float4* v_sm = (float4*)(smraw + 34816);
    float*  Ss   = (float*)(smraw + 51200);
    float*  m_s  = (float*)(smraw + 53760);
    float*  l_s  = m_s + 8;
    float*  f_s  = m_s + 16;
    float4* red  = (float4*)(smraw + 53856);

    int bh = blockIdx.x;
    int s  = blockIdx.y;
    int b = bh >> 4, h = bh & 15;
    int t = threadIdx.x, lane = t & 31, wid = t >> 5;

    // load q (scale folded: 1/sqrt(64) = 0.125)
    for (int i = t; i < 512; i += 256) {
        int j = i >> 6, d = i & 63;
        qs[i] = g_qkv[(size_t)(b * 8 + j) * 3072 + h * 64 + d] * 0.125f;
    }
    if (t < 8) { m_s[t] = -3.0e38f; l_s[t] = 0.f; }

    const float4* ksrc = (const float4*)past_k + (size_t)bh * TPAST * 16;
    const float4* vsrc = (const float4*)past_v + (size_t)bh * TPAST * 16;
    float4* kdst = (float4*)kout + (size_t)bh * TFULL * 16;
    float4* vdst = (float4*)vout + (size_t)bh * TFULL * 16;
    const float4* q4 = (const float4*)qs;
    const float2* v2s = (const float2*)v_sm;

    const int ld_r = t >> 4, ld_d4 = t & 15;
    uint32_t k_b0 = smem_u32(k_sm), v_b0 = smem_u32(v_sm);

    const int j2 = (wid & 3) * 2;
    const int r_sc = (wid >> 2) * 32 + lane;
    const int jp = t >> 6;
    const int rh = (t >> 5) & 1;
    const int d2 = lane;

    float accA0 = 0.f, accA1 = 0.f, accB0 = 0.f, accB1 = 0.f;

    const int c_begin = s * (TPAST / ASPLIT);

    // prefetch k chunk 0
    #pragma unroll
    for (int it = 0; it < 4; it++) {
        int r = ld_r + it * 16;
        int sw = r * 16 + (ld_d4 ^ (r & 15));
        cp16(k_b0 + (uint32_t)sw * 16, ksrc + (size_t)(c_begin + r) * 16 + ld_d4);
    }
    cp_commit();

    for (int ci = 0; ci < NCH; ci++) {
        int c0 = c_begin + ci * 64;
        int buf = ci & 1;
        cp_wait<0>();          // only k(ci) outstanding here
        __syncthreads();       // sync_a: k(ci) visible; accum(ci-1) done

        // issue v(ci) into the single v buffer (now safe to overwrite)
        #pragma unroll
        for (int it = 0; it < 4; it++) {
            int r = ld_r + it * 16;
            int sw = r * 16 + (ld_d4 ^ (r & 15));
            cp16(v_b0 + (uint32_t)sw * 16, vsrc + (size_t)(c0 + r) * 16 + ld_d4);
        }
        cp_commit();

        bool more = (ci + 1 < NCH);
        if (more) {            // prefetch k(ci+1) into the other k buffer
            uint32_t kb = k_b0 + (uint32_t)(buf ^ 1) * 16384;
            #pragma unroll
            for (int it = 0; it < 4; it++) {
                int r = ld_r + it * 16;
                int sw = r * 16 + (ld_d4 ^ (r & 15));
                cp16(kb + (uint32_t)sw * 16, ksrc + (size_t)(c0 + 64 + r) * 16 + ld_d4);
            }
            cp_commit();
        }

        const float4* kbp = k_sm + buf * 1024;

        // ---- copy k chunk to cache (streaming STG from smem) ----
        #pragma unroll
        for (int it = 0; it < 4; it++) {
            int r = ld_r + it * 16;
            int sw = r * 16 + (ld_d4 ^ (r & 15));
            __stcs(&kdst[(size_t)(c0 + r) * 16 + ld_d4], kbp[sw]);
        }

        // ---- scores: warp-uniform q (broadcast LDS), per-lane key ----
        {
            int r = r_sc;
            float s0 = 0.f, s1 = 0.f;
            #pragma unroll
            for (int d4 = 0; d4 < 16; d4++) {
                float4 kv = kbp[r * 16 + (d4 ^ (r & 15))];
                float4 qa = q4[j2 * 16 + d4];
                float4 qb = q4[(j2 + 1) * 16 + d4];
                s0 += kv.x * qa.x + kv.y * qa.y + kv.z * qa.z + kv.w * qa.w;
                s1 += kv.x * qb.x + kv.y * qb.y + kv.z * qb.z + kv.w * qb.w;
            }
            Ss[r * 10 + j2]     = s0;
            Ss[r * 10 + j2 + 1] = s1;
        }
        __syncthreads();       // sync_b: scores written
        softmax_update10(Ss, m_s, l_s, f_s, lane, wid);
        if (more) cp_wait<1>(); else cp_wait<0>();   // v(ci) arrived
        __syncthreads();       // sync_c: p, f, and v visible

        {
            float f0 = f_s[2 * jp], f1 = f_s[2 * jp + 1];
            accA0 *= f0; accA1 *= f0; accB0 *= f1; accB1 *= f1;
        }
        // ---- copy v chunk to cache ----
        #pragma unroll
        for (int it = 0; it < 4; it++) {
            int r = ld_r + it * 16;
            int sw = r * 16 + (ld_d4 ^ (r & 15));
            __stcs(&vdst[(size_t)(c0 + r) * 16 + ld_d4], v_sm[sw]);
        }
        // ---- accumulate: p pair broadcast, v float2 shared by 2 queries ----
        {
            int d4 = d2 >> 1, dlo = d2 & 1;
            #pragma unroll 8
            for (int rr = 0; rr < 32; rr++) {
                int r = rh * 32 + rr;
                float2 p = *(const float2*)&Ss[r * 10 + 2 * jp];
                float2 vv = v2s[(r * 16 + (d4 ^ (r & 15))) * 2 + dlo];
                accA0 += p.x * vv.x; accA1 += p.x * vv.y;
                accB0 += p.y * vv.x; accB1 += p.y * vv.y;
            }
        }
        // no trailing sync: next iteration's sync_a orders accum vs reuse
    }
    __syncthreads();           // protect k_sm/v_sm before tail reuse

    // =================== last split: 8 new keys (causal mask) ==============
    if (s == ASPLIT - 1) {
        if (t < 128) {
            int r = t >> 4, d4 = t & 15;
            k_sm[r * 16 + (d4 ^ (r & 15))] = kdst[(size_t)(TPAST + r) * 16 + d4];
        } else {
            int tt = t - 128;
            int r = tt >> 4, d4 = tt & 15;
            v_sm[r * 16 + (d4 ^ (r & 15))] = vdst[(size_t)(TPAST + r) * 16 + d4];
        }
        __syncthreads();
        {
            int r = r_sc;
            float s0 = -3.0e38f, s1 = -3.0e38f;
            if (r < 8) {
                float a0 = 0.f, a1 = 0.f;
                #pragma unroll
                for (int d4 = 0; d4 < 16; d4++) {
                    float4 kv = k_sm[r * 16 + (d4 ^ (r & 15))];
                    float4 qa = q4[j2 * 16 + d4];
                    float4 qb = q4[(j2 + 1) * 16 + d4];
                    a0 += kv.x * qa.x + kv.y * qa.y + kv.z * qa.z + kv.w * qa.w;
                    a1 += kv.x * qb.x + kv.y * qb.y + kv.z * qb.z + kv.w * qb.w;
                }
                if (r <= j2)     s0 = a0;
                if (r <= j2 + 1) s1 = a1;
            }
            Ss[r * 10 + j2]     = s0;
            Ss[r * 10 + j2 + 1] = s1;
        }
        __syncthreads();
        softmax_update10(Ss, m_s, l_s, f_s, lane, wid);
        __syncthreads();
        {
            float f0 = f_s[2 * jp], f1 = f_s[2 * jp + 1];
            accA0 *= f0; accA1 *= f0; accB0 *= f1; accB1 *= f1;
        }
        if (rh == 0) {
            int d4 = d2 >> 1, dlo = d2 & 1;
            #pragma unroll
            for (int r = 0; r < 8; r++) {
                float2 p = *(const float2*)&Ss[r * 10 + 2 * jp];
                float2 vv = v2s[(r * 16 + (d4 ^ (r & 15))) * 2 + dlo];
                accA0 += p.x * vv.x; accA1 += p.x * vv.y;
                accB0 += p.y * vv.x; accB1 += p.y * vv.y;
            }
        }
        __syncthreads();
    }

    // cross-half reduce + store partials
    if (rh == 1) red[jp * 32 + d2] = make_float4(accA0, accA1, accB0, accB1);
    __syncthreads();
    if (rh == 0) {
        float4 o = red[jp * 32 + d2];
        accA0 += o.x; accA1 += o.y; accB0 += o.z; accB1 += o.w;
        int j0 = 2 * jp, j1 = 2 * jp + 1;
        size_t base = (size_t)(bh * ASPLIT + s) * 8;
        g_po[(base + j0) * 64 + 2 * d2]     = accA0;
        g_po[(base + j0) * 64 + 2 * d2 + 1] = accA1;
        g_po[(base + j1) * 64 + 2 * d2]     = accB0;
        g_po[(base + j1) * 64 + 2 * d2 + 1] = accB1;
    }
    if (t < 8) {
        g_pm[(bh * ASPLIT + s) * 8 + t] = m_s[t];
        g_pl[(bh * ASPLIT + s) * 8 + t] = l_s[t];
    }
}

// combine split partials -> g_y (token-major for projection GEMM)
__global__ void __launch_bounds__(512) attn_combine()
{
    int bh = blockIdx.x;
    int b = bh >> 4, h = bh & 15;
    int t = threadIdx.x;
    int j = t >> 6, d = t & 63;

    float mm[ASPLIT], ll[ASPLIT];
    float m_g = -3.0e38f;
    #pragma unroll
    for (int s = 0; s < ASPLIT; s++) {
        mm[s] = g_pm[(bh * ASPLIT + s) * 8 + j];
        ll[s] = g_pl[(bh * ASPLIT + s) * 8 + j];
        m_g = fmaxf(m_g, mm[s]);
    }
    float l_g = 0.f, o = 0.f;
    #pragma unroll
    for (int s = 0; s < ASPLIT; s++) {
        float w = __expf(mm[s] - m_g);
        l_g += ll[s] * w;
        o += g_po[((size_t)(bh * ASPLIT + s) * 8 + j) * 64 + d] * w;
    }
    g_y[(size_t)(b * 8 + j) * Cdim + h * 64 + d] = o / l_g;
}

// ---------------------------------------------------------------------------
// kernel_launch (single stream):
//   gemm_mma(qkv) -> reduce_qkv(+scatter) -> attn_split -> attn_combine
//   -> gemm_mma(proj) -> reduce_proj
// ---------------------------------------------------------------------------
extern "C" void kernel_launch(void* const* d_in, const int* in_sizes, int n_in,
                              void* d_out, int out_size)
{
    const float* x      = (const float*)d_in[0];
    const float* past_k = (const float*)d_in[1];
    const float* past_v = (const float*)d_in[2];
    const float* W_attn = (const float*)d_in[3];
    const float* b_attn = (const float*)d_in[4];
    const float* W_proj = (const float*)d_in[5];
    const float* b_proj = (const float*)d_in[6];

    float* out  = (float*)d_out;
    float* kout = out + (size_t)NTOK * Cdim;
    float* vout = kout + (size_t)BHN * TFULL * HD;

    float* qkv_ptr = nullptr;
    float* y_ptr   = nullptr;
    float* pp_ptr  = nullptr;
    cudaGetSymbolAddress((void**)&qkv_ptr, g_qkv);
    cudaGetSymbolAddress((void**)&y_ptr, g_y);
    cudaGetSymbolAddress((void**)&pp_ptr, g_part);

    static int init_done = 0;
    if (!init_done) {
        cudaFuncSetAttribute(attn_split,
            cudaFuncAttributeMaxDynamicSharedMemorySize, ATTN_SMEM);
        init_done = 1;
    }

    // 1) QKV projection via tf32 split-MMA (split-K, KC=128)
    gemm_mma_splitk<<<dim3(48, KSQ), 256>>>(x, W_attn, pp_ptr, 3072, 1024, 128);
    reduce_qkv<<<384, 256>>>(pp_ptr, b_attn, qkv_ptr, kout, vout);

    // 2) fused cache copy + pipelined split attention + combine
    attn_split<<<dim3(BHN, ASPLIT), 256, ATTN_SMEM>>>(past_k, past_v, kout, vout);
    attn_combine<<<BHN, 512>>>();

    // 3) output projection via tf32 split-MMA (split-K, KC=64)
    gemm_mma_splitk<<<dim3(16, KSP), 256>>>(y_ptr, W_proj, pp_ptr, 1024, 1024, 64);
    reduce_proj<<<128, 256>>>(pp_ptr, b_proj, out);
}